// round 11
// baseline (speedup 1.0000x reference)
#include <cuda_runtime.h>
#include <cstdint>

#define N_  32768
#define NZ_ 512
#define H_  1024
#define C_  128
#define K_  8
#define TPB 256
#define BM  128          // rows per CTA
#define BH  128          // h columns per chunk
#define LDT 36           // staging tile pitch (floats): 32 + 4 pad
#define LDH 132          // h buffer pitch (floats): 128 + 4 pad

// ---------------- device scratch (static globals: allowed) -----------------
__device__ float g_q[N_ * K_];
__device__ float g_zt[N_ * NZ_];         // tf32-rounded z, fragment-permuted cols
__device__ float g_w1t[K_ * H_ * NZ_];   // [K][H][NZ]  (tf32-rounded, n-major)
__device__ float g_w2t[K_ * C_ * H_];    // [K][C][H]   (tf32-rounded, n-major)

// ---------------- helpers ---------------------------------------------------
__device__ __forceinline__ uint32_t smem_u32(const void* p) {
    uint32_t a;
    asm("{ .reg .u64 t; cvta.to.shared.u64 t, %1; cvt.u32.u64 %0, t; }" : "=r"(a) : "l"(p));
    return a;
}
__device__ __forceinline__ float tf32r(float x) {
    uint32_t u; asm("cvt.rna.tf32.f32 %0, %1;" : "=r"(u) : "f"(x));
    return __uint_as_float(u);
}
__device__ __forceinline__ void cp16(uint32_t s, const void* g) {
    asm volatile("cp.async.cg.shared.global [%0], [%1], 16;" :: "r"(s), "l"(g) : "memory");
}
#define CP_COMMIT() asm volatile("cp.async.commit_group;" ::: "memory")
#define CP_WAIT2()  asm volatile("cp.async.wait_group 2;" ::: "memory")

__device__ __forceinline__ void ldsm4(uint32_t* r, uint32_t a) {
    asm volatile("ldmatrix.sync.aligned.m8n8.x4.shared.b16 {%0,%1,%2,%3}, [%4];"
                 : "=r"(r[0]), "=r"(r[1]), "=r"(r[2]), "=r"(r[3]) : "r"(a));
}

// m16n8k8 tf32 mma: A row-major (4 regs), B col-major i.e. [n][k] (2 regs)
__device__ __forceinline__ void mma8(float* c, const uint32_t* a, uint32_t b0, uint32_t b1) {
    asm volatile(
        "mma.sync.aligned.m16n8k8.row.col.f32.tf32.tf32.f32 "
        "{%0,%1,%2,%3}, {%4,%5,%6,%7}, {%8,%9}, {%0,%1,%2,%3};"
        : "+f"(c[0]), "+f"(c[1]), "+f"(c[2]), "+f"(c[3])
        : "r"(a[0]), "r"(a[1]), "r"(a[2]), "r"(a[3]), "r"(b0), "r"(b1));
}

// ---------------------------------------------------------------------------
// prep_kernel: all preprocessing in ONE kernel (phase by blockIdx.x)
//   phase 0 [0, 16384):          z -> g_zt  (tf32 round + fragment col-permute)
//   phase 1 [16384, 20480):      W1 [K,NZ,H] -> g_w1t [K,H,NZ]
//   phase 2 [20480, 21504):      W2 [K,H,C]  -> g_w2t [K,C,H]
//   phase 3 [21504, 25600):      q
// column permute (per 8-col group): orig c -> pos 2*(c%4) + (c>=4), so lane
// pair (tig, tig+4) is contiguous float2 -> full-sector LDG.64 A fragments.
// ---------------------------------------------------------------------------
#define NB_Z  16384
#define NB_T1 4096
#define NB_T2 1024
#define NB_Q  4096

__global__ void prep_kernel(const float* __restrict__ z, const float* __restrict__ mu,
                            const float* __restrict__ W1, const float* __restrict__ W2) {
    __shared__ float t[32][33];
    __shared__ float smu[K_ * NZ_];
    const int bid = blockIdx.x;
    const int tid = threadIdx.x;

    if (bid < NB_Z) {
        int i = bid * TPB + tid;           // float4 index into z
        float4 v = ((const float4*)z)[i];
        int col = (i & (NZ_ / 4 - 1)) * 4; // 0..508, multiple of 4
        int row = i >> 7;                  // NZ_/4 = 128
        int j = col >> 3;                  // 8-col group
        int ro = (col & 7) >> 2;           // 0 if cols 0-3 of group, 1 if 4-7
        float* dst = g_zt + (size_t)row * NZ_ + j * 8 + ro;
        dst[0] = tf32r(v.x); dst[2] = tf32r(v.y);
        dst[4] = tf32r(v.z); dst[6] = tf32r(v.w);
        return;
    }
    if (bid < NB_Z + NB_T1) {              // W1 transpose: R=NZ_, Cc=H_
        int i = bid - NB_Z;
        int xx = i & 31;                   // H tiles (H_/32 = 32)
        int yy = (i >> 5) & 15;            // NZ tiles (NZ_/32 = 16)
        int b  = i >> 9;                   // expert
        int r0 = yy * 32, c0 = xx * 32;
        const float* s = W1 + (size_t)b * NZ_ * H_;
        float* d = g_w1t + (size_t)b * NZ_ * H_;
        int tx = tid & 31, ty = tid >> 5;  // 32 x 8
#pragma unroll
        for (int ii = 0; ii < 32; ii += 8)
            t[ty + ii][tx] = tf32r(s[(size_t)(r0 + ty + ii) * H_ + c0 + tx]);
        __syncthreads();
#pragma unroll
        for (int ii = 0; ii < 32; ii += 8)
            d[(size_t)(c0 + ty + ii) * NZ_ + r0 + tx] = t[tx][ty + ii];
        return;
    }
    if (bid < NB_Z + NB_T1 + NB_T2) {      // W2 transpose: R=H_, Cc=C_
        int i = bid - NB_Z - NB_T1;
        int xx = i & 3;                    // C tiles (C_/32 = 4)
        int yy = (i >> 2) & 31;            // H tiles (H_/32 = 32)
        int b  = i >> 7;                   // expert
        int r0 = yy * 32, c0 = xx * 32;
        const float* s = W2 + (size_t)b * H_ * C_;
        float* d = g_w2t + (size_t)b * H_ * C_;
        int tx = tid & 31, ty = tid >> 5;
#pragma unroll
        for (int ii = 0; ii < 32; ii += 8)
            t[ty + ii][tx] = tf32r(s[(size_t)(r0 + ty + ii) * C_ + c0 + tx]);
        __syncthreads();
#pragma unroll
        for (int ii = 0; ii < 32; ii += 8)
            d[(size_t)(c0 + ty + ii) * H_ + r0 + tx] = t[tx][ty + ii];
        return;
    }
    {   // q phase
        int qb = bid - NB_Z - NB_T1 - NB_T2;
        for (int i = tid; i < K_ * NZ_; i += TPB) smu[i] = mu[i];
        __syncthreads();
        int gwarp = (qb * TPB + tid) >> 5;
        int lane  = tid & 31;
        if (gwarp >= N_) return;
        const float* zr = z + (size_t)gwarp * NZ_;
        float acc[K_];
#pragma unroll
        for (int k = 0; k < K_; k++) acc[k] = 0.f;
        for (int j = lane; j < NZ_; j += 32) {
            float zj = zr[j];
#pragma unroll
            for (int k = 0; k < K_; k++) {
                float d = zj - smu[k * NZ_ + j];
                acc[k] = fmaf(d, d, acc[k]);
            }
        }
#pragma unroll
        for (int k = 0; k < K_; k++)
#pragma unroll
            for (int o = 16; o > 0; o >>= 1)
                acc[k] += __shfl_xor_sync(0xffffffffu, acc[k], o);
        if (lane == 0) {
            float w[K_], s = 0.f;
#pragma unroll
            for (int k = 0; k < K_; k++) { w[k] = 1.f / (1.f + acc[k]); s += w[k]; }
            float inv = 1.f / s;
#pragma unroll
            for (int k = 0; k < K_; k++) g_q[gwarp * K_ + k] = w[k] * inv;
        }
    }
}

// ---------------------------------------------------------------------------
// fused mma.sync tf32: A fragments via direct LDG.64 from permuted g_zt
// (no A smem staging); B via 4-stage B-only cp.async + ldmatrix.
// ---------------------------------------------------------------------------
#define STG_BYTES 18432                    // per stage: B tile only
#define OFF_HS    (4 * STG_BYTES)          // 73728
#define OFF_B2S   (OFF_HS + 128 * LDH * 4) // 141312
#define OFF_B1S   (OFF_B2S + 4096)         // 145408
#define SMEM_DYN  (146 * 1024)

#define ISSUE1(ss, st) do {                                                   \
    const int zb_ = (ss) * 32;                                                \
    const uint32_t ub_ = uST[st];                                             \
    _Pragma("unroll")                                                         \
    for (int v = 0; v < 4; v++) {                                             \
        int lin = tid + v * TPB;                                              \
        int row = lin >> 3, seg = lin & 7;                                    \
        cp16(ub_ + row * (LDT * 4) + seg * 16,                                \
             w1base + (size_t)(ht + row) * NZ_ + zb_ + seg * 4);              \
    }                                                                         \
} while (0)

#define ISSUE2(ss, st) do {                                                   \
    const int hb_ = (ss) * 32;                                                \
    const uint32_t ub_ = uST[st];                                             \
    _Pragma("unroll")                                                         \
    for (int v = 0; v < 4; v++) {                                             \
        int lin = tid + v * TPB;                                              \
        int row = lin >> 3, seg = lin & 7;                                    \
        cp16(ub_ + row * (LDT * 4) + seg * 16,                                \
             w2base + (size_t)row * H_ + ht + hb_ + seg * 4);                 \
    }                                                                         \
} while (0)

__global__ void __launch_bounds__(TPB, 1) fused_mma(
    const float* __restrict__ b1, const float* __restrict__ b2,
    float* __restrict__ out)
{
    extern __shared__ char sm[];
    float* const hs  = (float*)(sm + OFF_HS);
    float* const b2s = (float*)(sm + OFF_B2S);
    float* const b1s = (float*)(sm + OFF_B1S);

    const uint32_t sb = smem_u32(sm);
    const uint32_t uST[4] = { sb, sb + STG_BYTES, sb + 2 * STG_BYTES, sb + 3 * STG_BYTES };
    const uint32_t uHS = sb + OFF_HS;

    const int tid  = threadIdx.x;
    const int lane = tid & 31;
    const int warp = tid >> 5;
    const int wm   = warp & 3;       // 0..3 -> row block of 32
    const int wn   = warp >> 2;      // 0..1 -> col block of 64
    const int gr   = lane >> 2;      // group id 0..7
    const int tig  = lane & 3;       // thread in group
    const int rbase = wm * 32;
    const int cbase = wn * 64;
    const int n0   = blockIdx.x * BM;

    // ldmatrix per-lane offsets (bytes)
    const int lr = lane & 7;
    const int lg = lane >> 3;
    const uint32_t aOffH = (uint32_t)(((lr + (lg & 1) * 8) * LDH + (lg >> 1) * 4) * 4);
    const uint32_t bOffT = (uint32_t)(((lr + (lg >> 1) * 8) * LDT + (lg & 1) * 4) * 4);

    // A-fragment row pointers (permuted g_zt): rows rbase+gr (+8/+16/+24)
    const float* zr0 = g_zt + (size_t)(n0 + rbase + gr) * NZ_;
    const float* zr1 = zr0 + 8 * NZ_;
    const float* zr2 = zr0 + 16 * NZ_;
    const float* zr3 = zr0 + 24 * NZ_;

    for (int i = tid; i < K_ * C_; i += TPB) b2s[i] = b2[i];

    float outacc[64];
#pragma unroll
    for (int i = 0; i < 64; i++) outacc[i] = 0.f;

    for (int k = 0; k < K_; k++) {
        const float* w1base = g_w1t + (size_t)k * H_ * NZ_;
        const float* w2base = g_w2t + (size_t)k * C_ * H_;

        for (int ht = 0; ht < H_; ht += BH) {
            __syncthreads();   // prev chunk fully consumed
            if (tid < BH) b1s[tid] = b1[k * H_ + ht + tid];

            float hacc[64];
#pragma unroll
            for (int i = 0; i < 64; i++) hacc[i] = 0.f;

            // ================= GEMM1: 16 K-subtiles, 4-stage B pipeline =====
            ISSUE1(0, 0); CP_COMMIT();
            ISSUE1(1, 1); CP_COMMIT();
            ISSUE1(2, 2); CP_COMMIT();
            for (int s = 0; s < 16; s++) {
                const int st = s & 3;
                const int zb = s * 32;
                CP_WAIT2();
                __syncthreads();
                if (s < 13) { ISSUE1(s + 3, (s + 3) & 3); }
                CP_COMMIT();
                // A fragments: 16 independent LDG.64 (permuted pairs)
                uint32_t afr[4][2][4];
#pragma unroll
                for (int k8 = 0; k8 < 4; k8++) {
                    const int co = zb + k8 * 8 + 2 * tig;
                    float2 p0 = *(const float2*)(zr0 + co);
                    float2 p1 = *(const float2*)(zr1 + co);
                    float2 p2 = *(const float2*)(zr2 + co);
                    float2 p3 = *(const float2*)(zr3 + co);
                    afr[k8][0][0] = __float_as_uint(p0.x);
                    afr[k8][0][1] = __float_as_uint(p1.x);
                    afr[k8][0][2] = __float_as_uint(p0.y);
                    afr[k8][0][3] = __float_as_uint(p1.y);
                    afr[k8][1][0] = __float_as_uint(p2.x);
                    afr[k8][1][1] = __float_as_uint(p3.x);
                    afr[k8][1][2] = __float_as_uint(p2.y);
                    afr[k8][1][3] = __float_as_uint(p3.y);
                }
#pragma unroll
                for (int k8 = 0; k8 < 4; k8++) {
                    uint32_t bb[4][4];
                    const uint32_t bbse = uST[st] + (uint32_t)(k8 * 32);
#pragma unroll
                    for (int p = 0; p < 4; p++)
                        ldsm4(bb[p], bbse + (uint32_t)((cbase + p * 16) * (LDT * 4)) + bOffT);
#pragma unroll
                    for (int p = 0; p < 4; p++) {
#pragma unroll
                        for (int hf = 0; hf < 2; hf++) {
                            const int tn = p * 2 + hf;
                            mma8(&hacc[tn * 4],       afr[k8][0], bb[p][hf * 2], bb[p][hf * 2 + 1]);
                            mma8(&hacc[(8 + tn) * 4], afr[k8][1], bb[p][hf * 2], bb[p][hf * 2 + 1]);
                        }
                    }
                }
            }

            // ---- hs = tf32(q * relu(hacc + b1)) ----
#pragma unroll
            for (int tm = 0; tm < 2; tm++) {
                int r0 = rbase + tm * 16 + gr;
                float qa = g_q[(size_t)(n0 + r0) * K_ + k];
                float qb = g_q[(size_t)(n0 + r0 + 8) * K_ + k];
#pragma unroll
                for (int tn = 0; tn < 8; tn++) {
                    int idx = (tm * 8 + tn) * 4;
                    int c0  = cbase + tn * 8 + 2 * tig;
                    float2 v0, v1;
                    v0.x = tf32r(fmaxf(hacc[idx + 0] + b1s[c0], 0.f) * qa);
                    v0.y = tf32r(fmaxf(hacc[idx + 1] + b1s[c0 + 1], 0.f) * qa);
                    v1.x = tf32r(fmaxf(hacc[idx + 2] + b1s[c0], 0.f) * qb);
                    v1.y = tf32r(fmaxf(hacc[idx + 3] + b1s[c0 + 1], 0.f) * qb);
                    *(float2*)&hs[r0 * LDH + c0] = v0;
                    *(float2*)&hs[(r0 + 8) * LDH + c0] = v1;
                }
            }
            __syncthreads();

            // ================= GEMM2: 4 K-subtiles, pipelined ===============
            ISSUE2(0, 0); CP_COMMIT();
            ISSUE2(1, 1); CP_COMMIT();
            ISSUE2(2, 2); CP_COMMIT();
            for (int s = 0; s < 4; s++) {
                CP_WAIT2();
                __syncthreads();
                if (s < 1) { ISSUE2(3, 3); }
                CP_COMMIT();
                const int hb = s * 32;
#pragma unroll
                for (int k8 = 0; k8 < 4; k8++) {
                    uint32_t a0[4], a1[4], bb[4][4];
                    const uint32_t hbse = uHS + (uint32_t)((hb + k8 * 8) * 4);
                    ldsm4(a0, hbse + (uint32_t)(rbase * (LDH * 4)) + aOffH);
                    ldsm4(a1, hbse + (uint32_t)((rbase + 16) * (LDH * 4)) + aOffH);
                    const uint32_t bbse = uST[s] + (uint32_t)(k8 * 32);
#pragma unroll
                    for (int p = 0; p < 4; p++)
                        ldsm4(bb[p], bbse + (uint32_t)((cbase + p * 16) * (LDT * 4)) + bOffT);
#pragma unroll
                    for (int p = 0; p < 4; p++) {
#pragma unroll
                        for (int hf = 0; hf < 2; hf++) {
                            const int tn = p * 2 + hf;
                            mma8(&outacc[tn * 4],       a0, bb[p][hf * 2], bb[p][hf * 2 + 1]);
                            mma8(&outacc[(8 + tn) * 4], a1, bb[p][hf * 2], bb[p][hf * 2 + 1]);
                        }
                    }
                }
            }
        } // ht
    } // experts

    // ---- epilogue: out = outacc + q @ b2 ----
#pragma unroll
    for (int tm = 0; tm < 2; tm++) {
        int r0 = rbase + tm * 16 + gr;
        float qa[K_], qb[K_];
#pragma unroll
        for (int k = 0; k < K_; k++) {
            qa[k] = g_q[(size_t)(n0 + r0) * K_ + k];
            qb[k] = g_q[(size_t)(n0 + r0 + 8) * K_ + k];
        }
#pragma unroll
        for (int tn = 0; tn < 8; tn++) {
            int idx = (tm * 8 + tn) * 4;
            int c0  = cbase + tn * 8 + 2 * tig;
            float v00 = outacc[idx + 0], v01 = outacc[idx + 1];
            float v10 = outacc[idx + 2], v11 = outacc[idx + 3];
#pragma unroll
            for (int k = 0; k < K_; k++) {
                v00 = fmaf(qa[k], b2s[k * C_ + c0],     v00);
                v01 = fmaf(qa[k], b2s[k * C_ + c0 + 1], v01);
                v10 = fmaf(qb[k], b2s[k * C_ + c0],     v10);
                v11 = fmaf(qb[k], b2s[k * C_ + c0 + 1], v11);
            }
            *(float2*)&out[(size_t)(n0 + r0) * C_ + c0]     = make_float2(v00, v01);
            *(float2*)&out[(size_t)(n0 + r0 + 8) * C_ + c0] = make_float2(v10, v11);
        }
    }
}

// ---------------------------------------------------------------------------
extern "C" void kernel_launch(void* const* d_in, const int* in_sizes, int n_in,
                              void* d_out, int out_size) {
    const float* z  = (const float*)d_in[0];  // [N, NZ]
    const float* mu = (const float*)d_in[1];  // [K, NZ]
    const float* W1 = (const float*)d_in[2];  // [K, NZ, H]
    const float* b1 = (const float*)d_in[3];  // [K, H]
    const float* W2 = (const float*)d_in[4];  // [K, H, C]
    const float* b2 = (const float*)d_in[5];  // [K, C]
    float* out = (float*)d_out;               // [N, C]

    cudaFuncSetAttribute(fused_mma, cudaFuncAttributeMaxDynamicSharedMemorySize, SMEM_DYN);

    prep_kernel<<<NB_Z + NB_T1 + NB_T2 + NB_Q, TPB>>>(z, mu, W1, W2);
    fused_mma<<<N_ / BM, TPB, SMEM_DYN>>>(b1, b2, out);
}

// round 12
// speedup vs baseline: 1.4693x; 1.4693x over previous
#include <cuda_runtime.h>
#include <cstdint>

#define N_  32768
#define NZ_ 512
#define H_  1024
#define C_  128
#define K_  8
#define TPB 512
#define BM  128          // rows per CTA
#define BH  128          // h columns per chunk
#define LDT 36           // staging tile pitch (floats): 32 + 4 pad
#define LDH 132          // h buffer pitch (floats): 128 + 4 pad

// ---------------- device scratch (static globals: allowed) -----------------
__device__ float g_q[N_ * K_];
__device__ float g_zt[N_ * NZ_];         // tf32-rounded z
__device__ float g_w1t[K_ * H_ * NZ_];   // [K][H][NZ]  (tf32-rounded, n-major)
__device__ float g_w2t[K_ * C_ * H_];    // [K][C][H]   (tf32-rounded, n-major)

// ---------------- helpers ---------------------------------------------------
__device__ __forceinline__ uint32_t smem_u32(const void* p) {
    uint32_t a;
    asm("{ .reg .u64 t; cvta.to.shared.u64 t, %1; cvt.u32.u64 %0, t; }" : "=r"(a) : "l"(p));
    return a;
}
__device__ __forceinline__ float tf32r(float x) {
    uint32_t u; asm("cvt.rna.tf32.f32 %0, %1;" : "=r"(u) : "f"(x));
    return __uint_as_float(u);
}
__device__ __forceinline__ void cp16(uint32_t s, const void* g) {
    asm volatile("cp.async.cg.shared.global [%0], [%1], 16;" :: "r"(s), "l"(g) : "memory");
}
#define CP_COMMIT() asm volatile("cp.async.commit_group;" ::: "memory")
#define CP_WAIT2()  asm volatile("cp.async.wait_group 2;" ::: "memory")

__device__ __forceinline__ void ldsm4(uint32_t* r, uint32_t a) {
    asm volatile("ldmatrix.sync.aligned.m8n8.x4.shared.b16 {%0,%1,%2,%3}, [%4];"
                 : "=r"(r[0]), "=r"(r[1]), "=r"(r[2]), "=r"(r[3]) : "r"(a));
}

// m16n8k8 tf32 mma: A row-major (4 regs), B col-major i.e. [n][k] (2 regs)
__device__ __forceinline__ void mma8(float* c, const uint32_t* a, uint32_t b0, uint32_t b1) {
    asm volatile(
        "mma.sync.aligned.m16n8k8.row.col.f32.tf32.tf32.f32 "
        "{%0,%1,%2,%3}, {%4,%5,%6,%7}, {%8,%9}, {%0,%1,%2,%3};"
        : "+f"(c[0]), "+f"(c[1]), "+f"(c[2]), "+f"(c[3])
        : "r"(a[0]), "r"(a[1]), "r"(a[2]), "r"(a[3]), "r"(b0), "r"(b1));
}

// ---------------------------------------------------------------------------
// prep_kernel: all preprocessing in ONE kernel (phase by blockIdx.x)
//   z -> g_zt (tf32 round, plain layout), W1/W2 transposes, q.
// ---------------------------------------------------------------------------
#define PREP_TPB 256
#define NB_Z  16384
#define NB_T1 4096
#define NB_T2 1024
#define NB_Q  4096

__global__ void prep_kernel(const float* __restrict__ z, const float* __restrict__ mu,
                            const float* __restrict__ W1, const float* __restrict__ W2) {
    __shared__ float t[32][33];
    __shared__ float smu[K_ * NZ_];
    const int bid = blockIdx.x;
    const int tid = threadIdx.x;

    if (bid < NB_Z) {
        int i = bid * PREP_TPB + tid;      // float4 index into z
        float4 v = ((const float4*)z)[i];
        v.x = tf32r(v.x); v.y = tf32r(v.y); v.z = tf32r(v.z); v.w = tf32r(v.w);
        ((float4*)g_zt)[i] = v;
        return;
    }
    if (bid < NB_Z + NB_T1) {              // W1 transpose: [K,NZ,H] -> [K,H,NZ]
        int i = bid - NB_Z;
        int xx = i & 31;                   // H tiles
        int yy = (i >> 5) & 15;            // NZ tiles
        int b  = i >> 9;                   // expert
        int r0 = yy * 32, c0 = xx * 32;
        const float* s = W1 + (size_t)b * NZ_ * H_;
        float* d = g_w1t + (size_t)b * NZ_ * H_;
        int tx = tid & 31, ty = tid >> 5;  // 32 x 8
#pragma unroll
        for (int ii = 0; ii < 32; ii += 8)
            t[ty + ii][tx] = tf32r(s[(size_t)(r0 + ty + ii) * H_ + c0 + tx]);
        __syncthreads();
#pragma unroll
        for (int ii = 0; ii < 32; ii += 8)
            d[(size_t)(c0 + ty + ii) * NZ_ + r0 + tx] = t[tx][ty + ii];
        return;
    }
    if (bid < NB_Z + NB_T1 + NB_T2) {      // W2 transpose: [K,H,C] -> [K,C,H]
        int i = bid - NB_Z - NB_T1;
        int xx = i & 3;                    // C tiles
        int yy = (i >> 2) & 31;            // H tiles
        int b  = i >> 7;                   // expert
        int r0 = yy * 32, c0 = xx * 32;
        const float* s = W2 + (size_t)b * H_ * C_;
        float* d = g_w2t + (size_t)b * H_ * C_;
        int tx = tid & 31, ty = tid >> 5;
#pragma unroll
        for (int ii = 0; ii < 32; ii += 8)
            t[ty + ii][tx] = tf32r(s[(size_t)(r0 + ty + ii) * C_ + c0 + tx]);
        __syncthreads();
#pragma unroll
        for (int ii = 0; ii < 32; ii += 8)
            d[(size_t)(c0 + ty + ii) * H_ + r0 + tx] = t[tx][ty + ii];
        return;
    }
    {   // q phase
        int qb = bid - NB_Z - NB_T1 - NB_T2;
        for (int i = tid; i < K_ * NZ_; i += PREP_TPB) smu[i] = mu[i];
        __syncthreads();
        int gwarp = (qb * PREP_TPB + tid) >> 5;
        int lane  = tid & 31;
        if (gwarp >= N_) return;
        const float* zr = z + (size_t)gwarp * NZ_;
        float acc[K_];
#pragma unroll
        for (int k = 0; k < K_; k++) acc[k] = 0.f;
        for (int j = lane; j < NZ_; j += 32) {
            float zj = zr[j];
#pragma unroll
            for (int k = 0; k < K_; k++) {
                float d = zj - smu[k * NZ_ + j];
                acc[k] = fmaf(d, d, acc[k]);
            }
        }
#pragma unroll
        for (int k = 0; k < K_; k++)
#pragma unroll
            for (int o = 16; o > 0; o >>= 1)
                acc[k] += __shfl_xor_sync(0xffffffffu, acc[k], o);
        if (lane == 0) {
            float w[K_], s = 0.f;
#pragma unroll
            for (int k = 0; k < K_; k++) { w[k] = 1.f / (1.f + acc[k]); s += w[k]; }
            float inv = 1.f / s;
#pragma unroll
            for (int k = 0; k < K_; k++) g_q[gwarp * K_ + k] = w[k] * inv;
        }
    }
}

// ---------------------------------------------------------------------------
// fused mma.sync tf32: 512 threads, 4x4 warp grid, 32x32 per-warp tiles.
// A+B staged 4-deep via cp.async; ldmatrix fragments; q folded into ReLU.
// ---------------------------------------------------------------------------
#define STG_BYTES 36864                    // per stage: A 18432 + B 18432
#define OFF_HS    (4 * STG_BYTES)          // 147456
#define OFF_B2S   (OFF_HS + 128 * LDH * 4) // 215040
#define OFF_B1S   (OFF_B2S + 4096)         // 219136
#define SMEM_DYN  (OFF_B1S + 512)          // 219648

#define ISSUE1(ss, st) do {                                                   \
    const int zb_ = (ss) * 32;                                                \
    const uint32_t ua_ = uST[st];                                             \
    const uint32_t ub_ = uST[st] + 18432;                                     \
    _Pragma("unroll")                                                         \
    for (int v = 0; v < 2; v++) {                                             \
        int lin = tid + v * TPB;                                              \
        int row = lin >> 3, seg = lin & 7;                                    \
        cp16(ua_ + row * (LDT * 4) + seg * 16,                                \
             g_zt + (size_t)(n0 + row) * NZ_ + zb_ + seg * 4);                \
    }                                                                         \
    _Pragma("unroll")                                                         \
    for (int v = 0; v < 2; v++) {                                             \
        int lin = tid + v * TPB;                                              \
        int row = lin >> 3, seg = lin & 7;                                    \
        cp16(ub_ + row * (LDT * 4) + seg * 16,                                \
             w1base + (size_t)(ht + row) * NZ_ + zb_ + seg * 4);              \
    }                                                                         \
} while (0)

#define ISSUE2(ss, st) do {                                                   \
    const int hb_ = (ss) * 32;                                                \
    const uint32_t ub_ = uST[st] + 18432;                                     \
    _Pragma("unroll")                                                         \
    for (int v = 0; v < 2; v++) {                                             \
        int lin = tid + v * TPB;                                              \
        int row = lin >> 3, seg = lin & 7;                                    \
        cp16(ub_ + row * (LDT * 4) + seg * 16,                                \
             w2base + (size_t)row * H_ + ht + hb_ + seg * 4);                 \
    }                                                                         \
} while (0)

__global__ void __launch_bounds__(TPB, 1) fused_mma(
    const float* __restrict__ b1, const float* __restrict__ b2,
    float* __restrict__ out)
{
    extern __shared__ char sm[];
    float* const hs  = (float*)(sm + OFF_HS);
    float* const b2s = (float*)(sm + OFF_B2S);
    float* const b1s = (float*)(sm + OFF_B1S);

    const uint32_t sb = smem_u32(sm);
    const uint32_t uST[4] = { sb, sb + STG_BYTES, sb + 2 * STG_BYTES, sb + 3 * STG_BYTES };
    const uint32_t uHS = sb + OFF_HS;

    const int tid  = threadIdx.x;
    const int lane = tid & 31;
    const int warp = tid >> 5;       // 0..15
    const int wm   = warp & 3;       // row block of 32
    const int wn   = warp >> 2;      // col block of 32
    const int gr   = lane >> 2;      // 0..7
    const int tig  = lane & 3;       // 0..3
    const int rbase = wm * 32;
    const int cbase = wn * 32;
    const int n0   = blockIdx.x * BM;

    // ldmatrix per-lane offsets (bytes)
    const int lr = lane & 7;
    const int lg = lane >> 3;
    const uint32_t aOffT = (uint32_t)(((lr + (lg & 1) * 8) * LDT + (lg >> 1) * 4) * 4);
    const uint32_t aOffH = (uint32_t)(((lr + (lg & 1) * 8) * LDH + (lg >> 1) * 4) * 4);
    const uint32_t bOffT = (uint32_t)(((lr + (lg >> 1) * 8) * LDT + (lg & 1) * 4) * 4);

    for (int i = tid; i < K_ * C_; i += TPB) b2s[i] = b2[i];

    float outacc[32];                 // 2 tm x 4 tn x 4
#pragma unroll
    for (int i = 0; i < 32; i++) outacc[i] = 0.f;

    for (int k = 0; k < K_; k++) {
        const float* w1base = g_w1t + (size_t)k * H_ * NZ_;
        const float* w2base = g_w2t + (size_t)k * C_ * H_;

        for (int ht = 0; ht < H_; ht += BH) {
            __syncthreads();   // prev chunk fully consumed
            if (tid < BH) b1s[tid] = b1[k * H_ + ht + tid];

            float hacc[32];
#pragma unroll
            for (int i = 0; i < 32; i++) hacc[i] = 0.f;

            // ================= GEMM1: 16 K-subtiles, 4-stage pipeline =======
            ISSUE1(0, 0); CP_COMMIT();
            ISSUE1(1, 1); CP_COMMIT();
            ISSUE1(2, 2); CP_COMMIT();
            for (int s = 0; s < 16; s++) {
                const int st = s & 3;
                CP_WAIT2();
                __syncthreads();
                if (s < 13) { ISSUE1(s + 3, (s + 3) & 3); }
                CP_COMMIT();
#pragma unroll
                for (int k8 = 0; k8 < 4; k8++) {
                    uint32_t a0[4], a1[4], bb[2][4];
                    const uint32_t ab = uST[st] + (uint32_t)(k8 * 32);
                    ldsm4(a0, ab + (uint32_t)(rbase * (LDT * 4)) + aOffT);
                    ldsm4(a1, ab + (uint32_t)((rbase + 16) * (LDT * 4)) + aOffT);
                    const uint32_t bbse = uST[st] + 18432u + (uint32_t)(k8 * 32);
                    ldsm4(bb[0], bbse + (uint32_t)(cbase * (LDT * 4)) + bOffT);
                    ldsm4(bb[1], bbse + (uint32_t)((cbase + 16) * (LDT * 4)) + bOffT);
#pragma unroll
                    for (int p = 0; p < 2; p++) {
#pragma unroll
                        for (int hf = 0; hf < 2; hf++) {
                            const int tn = p * 2 + hf;
                            mma8(&hacc[tn * 4],        a0, bb[p][hf * 2], bb[p][hf * 2 + 1]);
                            mma8(&hacc[(4 + tn) * 4],  a1, bb[p][hf * 2], bb[p][hf * 2 + 1]);
                        }
                    }
                }
            }

            // ---- hs = tf32(q * relu(hacc + b1)) ----
#pragma unroll
            for (int tm = 0; tm < 2; tm++) {
                int r0 = rbase + tm * 16 + gr;
                float qa = g_q[(size_t)(n0 + r0) * K_ + k];
                float qb = g_q[(size_t)(n0 + r0 + 8) * K_ + k];
#pragma unroll
                for (int tn = 0; tn < 4; tn++) {
                    int idx = (tm * 4 + tn) * 4;
                    int c0  = cbase + tn * 8 + 2 * tig;
                    float2 v0, v1;
                    v0.x = tf32r(fmaxf(hacc[idx + 0] + b1s[c0], 0.f) * qa);
                    v0.y = tf32r(fmaxf(hacc[idx + 1] + b1s[c0 + 1], 0.f) * qa);
                    v1.x = tf32r(fmaxf(hacc[idx + 2] + b1s[c0], 0.f) * qb);
                    v1.y = tf32r(fmaxf(hacc[idx + 3] + b1s[c0 + 1], 0.f) * qb);
                    *(float2*)&hs[r0 * LDH + c0] = v0;
                    *(float2*)&hs[(r0 + 8) * LDH + c0] = v1;
                }
            }
            __syncthreads();

            // ================= GEMM2: 4 K-subtiles, pipelined ===============
            ISSUE2(0, 0); CP_COMMIT();
            ISSUE2(1, 1); CP_COMMIT();
            ISSUE2(2, 2); CP_COMMIT();
            for (int s = 0; s < 4; s++) {
                CP_WAIT2();
                __syncthreads();
                if (s < 1) { ISSUE2(3, 3); }
                CP_COMMIT();
                const int hb = s * 32;
#pragma unroll
                for (int k8 = 0; k8 < 4; k8++) {
                    uint32_t a0[4], a1[4], bb[2][4];
                    const uint32_t hbse = uHS + (uint32_t)((hb + k8 * 8) * 4);
                    ldsm4(a0, hbse + (uint32_t)(rbase * (LDH * 4)) + aOffH);
                    ldsm4(a1, hbse + (uint32_t)((rbase + 16) * (LDH * 4)) + aOffH);
                    const uint32_t bbse = uST[s] + 18432u + (uint32_t)(k8 * 32);
                    ldsm4(bb[0], bbse + (uint32_t)(cbase * (LDT * 4)) + bOffT);
                    ldsm4(bb[1], bbse + (uint32_t)((cbase + 16) * (LDT * 4)) + bOffT);
#pragma unroll
                    for (int p = 0; p < 2; p++) {
#pragma unroll
                        for (int hf = 0; hf < 2; hf++) {
                            const int tn = p * 2 + hf;
                            mma8(&outacc[tn * 4],       a0, bb[p][hf * 2], bb[p][hf * 2 + 1]);
                            mma8(&outacc[(4 + tn) * 4], a1, bb[p][hf * 2], bb[p][hf * 2 + 1]);
                        }
                    }
                }
            }
        } // ht
    } // experts

    // ---- epilogue: out = outacc + q @ b2 ----
#pragma unroll
    for (int tm = 0; tm < 2; tm++) {
        int r0 = rbase + tm * 16 + gr;
        float qa[K_], qb[K_];
#pragma unroll
        for (int k = 0; k < K_; k++) {
            qa[k] = g_q[(size_t)(n0 + r0) * K_ + k];
            qb[k] = g_q[(size_t)(n0 + r0 + 8) * K_ + k];
        }
#pragma unroll
        for (int tn = 0; tn < 4; tn++) {
            int idx = (tm * 4 + tn) * 4;
            int c0  = cbase + tn * 8 + 2 * tig;
            float v00 = outacc[idx + 0], v01 = outacc[idx + 1];
            float v10 = outacc[idx + 2], v11 = outacc[idx + 3];
#pragma unroll
            for (int k = 0; k < K_; k++) {
                v00 = fmaf(qa[k], b2s[k * C_ + c0],     v00);
                v01 = fmaf(qa[k], b2s[k * C_ + c0 + 1], v01);
                v10 = fmaf(qb[k], b2s[k * C_ + c0],     v10);
                v11 = fmaf(qb[k], b2s[k * C_ + c0 + 1], v11);
            }
            *(float2*)&out[(size_t)(n0 + r0) * C_ + c0]     = make_float2(v00, v01);
            *(float2*)&out[(size_t)(n0 + r0 + 8) * C_ + c0] = make_float2(v10, v11);
        }
    }
}

// ---------------------------------------------------------------------------
extern "C" void kernel_launch(void* const* d_in, const int* in_sizes, int n_in,
                              void* d_out, int out_size) {
    const float* z  = (const float*)d_in[0];  // [N, NZ]
    const float* mu = (const float*)d_in[1];  // [K, NZ]
    const float* W1 = (const float*)d_in[2];  // [K, NZ, H]
    const float* b1 = (const float*)d_in[3];  // [K, H]
    const float* W2 = (const float*)d_in[4];  // [K, H, C]
    const float* b2 = (const float*)d_in[5];  // [K, C]
    float* out = (float*)d_out;               // [N, C]

    cudaFuncSetAttribute(fused_mma, cudaFuncAttributeMaxDynamicSharedMemorySize, SMEM_DYN);

    prep_kernel<<<NB_Z + NB_T1 + NB_T2 + NB_Q, PREP_TPB>>>(z, mu, W1, W2);
    fused_mma<<<N_ / BM, TPB, SMEM_DYN>>>(b1, b2, out);
}

// round 14
// speedup vs baseline: 2.5745x; 1.7522x over previous
#include <cuda_runtime.h>
#include <cuda_fp16.h>
#include <cstdint>

#define N_  32768
#define NZ_ 512
#define H_  1024
#define C_  128
#define K_  8
#define TPB 512
#define BM  128          // rows per CTA
#define BH  128          // h columns per chunk
#define KS  64           // K depth per stage (fp16: 128B rows)
#define PITB 144         // staging row pitch bytes (128B data + 16 pad)
#define LDHH 136         // hs pitch in halves (272B = 256 data + 16 pad)

// ---------------- device scratch (static globals: allowed) -----------------
__device__ float  g_q[N_ * K_];
__device__ __half g_zth[N_ * NZ_];         // fp16 z
__device__ __half g_w1th[K_ * H_ * NZ_];   // [K][H][NZ]  n-major fp16
__device__ __half g_w2th[K_ * C_ * H_];    // [K][C][H]   n-major fp16

// ---------------- helpers ---------------------------------------------------
__device__ __forceinline__ uint32_t smem_u32(const void* p) {
    uint32_t a;
    asm("{ .reg .u64 t; cvta.to.shared.u64 t, %1; cvt.u32.u64 %0, t; }" : "=r"(a) : "l"(p));
    return a;
}
__device__ __forceinline__ void cp16(uint32_t s, const void* g) {
    asm volatile("cp.async.cg.shared.global [%0], [%1], 16;" :: "r"(s), "l"(g) : "memory");
}
#define CP_COMMIT() asm volatile("cp.async.commit_group;" ::: "memory")
#define CP_WAIT2()  asm volatile("cp.async.wait_group 2;" ::: "memory")
#define CP_WAIT0()  asm volatile("cp.async.wait_group 0;" ::: "memory")

__device__ __forceinline__ void ldsm4(uint32_t* r, uint32_t a) {
    asm volatile("ldmatrix.sync.aligned.m8n8.x4.shared.b16 {%0,%1,%2,%3}, [%4];"
                 : "=r"(r[0]), "=r"(r[1]), "=r"(r[2]), "=r"(r[3]) : "r"(a));
}

// m16n8k16 fp16 mma, fp32 accum. A row-major (4 regs), B col-major [n][k] (2 regs)
__device__ __forceinline__ void mma16(float* c, const uint32_t* a, uint32_t b0, uint32_t b1) {
    asm volatile(
        "mma.sync.aligned.m16n8k16.row.col.f32.f16.f16.f32 "
        "{%0,%1,%2,%3}, {%4,%5,%6,%7}, {%8,%9}, {%0,%1,%2,%3};"
        : "+f"(c[0]), "+f"(c[1]), "+f"(c[2]), "+f"(c[3])
        : "r"(a[0]), "r"(a[1]), "r"(a[2]), "r"(a[3]), "r"(b0), "r"(b1));
}

// ---------------------------------------------------------------------------
// prep_kernel: z->fp16, W1/W2 transpose->fp16 n-major, q.  One kernel.
// ---------------------------------------------------------------------------
#define PREP_TPB 256
#define NB_Z  16384
#define NB_T1 4096
#define NB_T2 1024
#define NB_Q  4096

__global__ void prep_kernel(const float* __restrict__ z, const float* __restrict__ mu,
                            const float* __restrict__ W1, const float* __restrict__ W2) {
    __shared__ float t[32][33];
    __shared__ float smu[K_ * NZ_];
    const int bid = blockIdx.x;
    const int tid = threadIdx.x;

    if (bid < NB_Z) {
        int i = bid * PREP_TPB + tid;      // float4 index
        float4 v = ((const float4*)z)[i];
        __half2* dst = (__half2*)g_zth;
        dst[2 * i]     = __floats2half2_rn(v.x, v.y);
        dst[2 * i + 1] = __floats2half2_rn(v.z, v.w);
        return;
    }
    if (bid < NB_Z + NB_T1) {              // W1 [K,NZ,H] -> g_w1th [K,H,NZ]
        int i = bid - NB_Z;
        int xx = i & 31, yy = (i >> 5) & 15, b = i >> 9;
        int r0 = yy * 32, c0 = xx * 32;
        const float* s = W1 + (size_t)b * NZ_ * H_;
        __half* d = g_w1th + (size_t)b * NZ_ * H_;
        int tx = tid & 31, ty = tid >> 5;
#pragma unroll
        for (int ii = 0; ii < 32; ii += 8)
            t[ty + ii][tx] = s[(size_t)(r0 + ty + ii) * H_ + c0 + tx];
        __syncthreads();
#pragma unroll
        for (int ii = 0; ii < 32; ii += 8)
            d[(size_t)(c0 + ty + ii) * NZ_ + r0 + tx] = __float2half_rn(t[tx][ty + ii]);
        return;
    }
    if (bid < NB_Z + NB_T1 + NB_T2) {      // W2 [K,H,C] -> g_w2th [K,C,H]
        int i = bid - NB_Z - NB_T1;
        int xx = i & 3, yy = (i >> 2) & 31, b = i >> 7;
        int r0 = yy * 32, c0 = xx * 32;
        const float* s = W2 + (size_t)b * H_ * C_;
        __half* d = g_w2th + (size_t)b * H_ * C_;
        int tx = tid & 31, ty = tid >> 5;
#pragma unroll
        for (int ii = 0; ii < 32; ii += 8)
            t[ty + ii][tx] = s[(size_t)(r0 + ty + ii) * C_ + c0 + tx];
        __syncthreads();
#pragma unroll
        for (int ii = 0; ii < 32; ii += 8)
            d[(size_t)(c0 + ty + ii) * H_ + r0 + tx] = __float2half_rn(t[tx][ty + ii]);
        return;
    }
    {   // q
        int qb = bid - NB_Z - NB_T1 - NB_T2;
        for (int i = tid; i < K_ * NZ_; i += PREP_TPB) smu[i] = mu[i];
        __syncthreads();
        int gwarp = (qb * PREP_TPB + tid) >> 5;
        int lane  = tid & 31;
        if (gwarp >= N_) return;
        const float* zr = z + (size_t)gwarp * NZ_;
        float acc[K_];
#pragma unroll
        for (int k = 0; k < K_; k++) acc[k] = 0.f;
        for (int j = lane; j < NZ_; j += 32) {
            float zj = zr[j];
#pragma unroll
            for (int k = 0; k < K_; k++) {
                float d = zj - smu[k * NZ_ + j];
                acc[k] = fmaf(d, d, acc[k]);
            }
        }
#pragma unroll
        for (int k = 0; k < K_; k++)
#pragma unroll
            for (int o = 16; o > 0; o >>= 1)
                acc[k] += __shfl_xor_sync(0xffffffffu, acc[k], o);
        if (lane == 0) {
            float w[K_], s = 0.f;
#pragma unroll
            for (int k = 0; k < K_; k++) { w[k] = 1.f / (1.f + acc[k]); s += w[k]; }
            float inv = 1.f / s;
#pragma unroll
            for (int k = 0; k < K_; k++) g_q[gwarp * K_ + k] = w[k] * inv;
        }
    }
}

// ---------------------------------------------------------------------------
// fused fp16 mma: 512 threads, 4x4 warps, 32x32 tiles, m16n8k16,
// 4-stage cp.async (K=64/stage), q folded into ReLU.
// ---------------------------------------------------------------------------
#define STG_BYTES (2 * 128 * PITB)            // A 18432 + B 18432 = 36864
#define OFF_HS    (4 * STG_BYTES)             // 147456
#define OFF_B2S   (OFF_HS + 128 * LDHH * 2)   // 147456 + 34816 = 182272
#define OFF_B1S   (OFF_B2S + 4096)            // 186368
#define SMEM_DYN  (OFF_B1S + 512)             // 186880

#define ISSUE1(ss, st) do {                                                   \
    const int zb_ = (ss) * KS;                                                \
    const uint32_t ua_ = uST[st];                                             \
    const uint32_t ub_ = uST[st] + 128 * PITB;                                \
    _Pragma("unroll")                                                         \
    for (int v = 0; v < 2; v++) {                                             \
        int lin = tid + v * TPB;                                              \
        int row = lin >> 3, seg = lin & 7;                                    \
        cp16(ua_ + row * PITB + seg * 16,                                     \
             g_zth + (size_t)(n0 + row) * NZ_ + zb_ + seg * 8);               \
    }                                                                         \
    _Pragma("unroll")                                                         \
    for (int v = 0; v < 2; v++) {                                             \
        int lin = tid + v * TPB;                                              \
        int row = lin >> 3, seg = lin & 7;                                    \
        cp16(ub_ + row * PITB + seg * 16,                                     \
             w1base + (size_t)(ht + row) * NZ_ + zb_ + seg * 8);              \
    }                                                                         \
} while (0)

#define ISSUE2(ss, st) do {                                                   \
    const int hb_ = (ss) * KS;                                                \
    const uint32_t ub_ = uST[st];                                             \
    _Pragma("unroll")                                                         \
    for (int v = 0; v < 2; v++) {                                             \
        int lin = tid + v * TPB;                                              \
        int row = lin >> 3, seg = lin & 7;                                    \
        cp16(ub_ + row * PITB + seg * 16,                                     \
             w2base + (size_t)row * H_ + ht + hb_ + seg * 8);                 \
    }                                                                         \
} while (0)

__global__ void __launch_bounds__(TPB, 1) fused_mma(
    const float* __restrict__ b1, const float* __restrict__ b2,
    float* __restrict__ out)
{
    extern __shared__ char sm[];
    __half* const hs  = (__half*)(sm + OFF_HS);
    float*  const b2s = (float*)(sm + OFF_B2S);
    float*  const b1s = (float*)(sm + OFF_B1S);

    const uint32_t sb = smem_u32(sm);
    const uint32_t uST[4] = { sb, sb + STG_BYTES, sb + 2 * STG_BYTES, sb + 3 * STG_BYTES };
    const uint32_t uHS = sb + OFF_HS;

    const int tid  = threadIdx.x;
    const int lane = tid & 31;
    const int warp = tid >> 5;       // 0..15
    const int wm   = warp & 3;       // row block of 32
    const int wn   = warp >> 2;      // col block of 32
    const int gr   = lane >> 2;      // 0..7
    const int tig  = lane & 3;       // 0..3
    const int rbase = wm * 32;
    const int cbase = wn * 32;
    const int n0   = blockIdx.x * BM;

    // ldmatrix lane offsets (bytes)
    const int lr = lane & 7;
    const int lg = lane >> 3;
    const uint32_t aOffT = (uint32_t)((lr + (lg & 1) * 8) * PITB + (lg >> 1) * 16);
    const uint32_t aOffH = (uint32_t)((lr + (lg & 1) * 8) * (LDHH * 2) + (lg >> 1) * 16);
    const uint32_t bOffT = (uint32_t)((lr + (lg >> 1) * 8) * PITB + (lg & 1) * 16);

    for (int i = tid; i < K_ * C_; i += TPB) b2s[i] = b2[i];

    float outacc[32];
#pragma unroll
    for (int i = 0; i < 32; i++) outacc[i] = 0.f;

    for (int k = 0; k < K_; k++) {
        const __half* w1base = g_w1th + (size_t)k * H_ * NZ_;
        const __half* w2base = g_w2th + (size_t)k * C_ * H_;

        for (int ht = 0; ht < H_; ht += BH) {
            __syncthreads();   // prev chunk fully consumed
            if (tid < BH) b1s[tid] = b1[k * H_ + ht + tid];

            float hacc[32];
#pragma unroll
            for (int i = 0; i < 32; i++) hacc[i] = 0.f;

            // ========== GEMM1: 8 K-subtiles of 64, 4-stage pipeline ========
            ISSUE1(0, 0); CP_COMMIT();
            ISSUE1(1, 1); CP_COMMIT();
            ISSUE1(2, 2); CP_COMMIT();
            for (int s = 0; s < 8; s++) {
                const int st = s & 3;
                CP_WAIT2();
                __syncthreads();
                if (s < 5) { ISSUE1(s + 3, (s + 3) & 3); }
                CP_COMMIT();
#pragma unroll
                for (int kk = 0; kk < 4; kk++) {   // k16 blocks within K=64
                    uint32_t a0[4], a1[4], bb0[4], bb1[4];
                    const uint32_t ab = uST[st] + (uint32_t)(kk * 32);
                    ldsm4(a0, ab + (uint32_t)(rbase * PITB) + aOffT);
                    ldsm4(a1, ab + (uint32_t)((rbase + 16) * PITB) + aOffT);
                    const uint32_t bbse = uST[st] + (uint32_t)(128 * PITB) + (uint32_t)(kk * 32);
                    ldsm4(bb0, bbse + (uint32_t)(cbase * PITB) + bOffT);
                    ldsm4(bb1, bbse + (uint32_t)((cbase + 16) * PITB) + bOffT);
                    mma16(&hacc[0],  a0, bb0[0], bb0[1]);
                    mma16(&hacc[4],  a0, bb0[2], bb0[3]);
                    mma16(&hacc[8],  a0, bb1[0], bb1[1]);
                    mma16(&hacc[12], a0, bb1[2], bb1[3]);
                    mma16(&hacc[16], a1, bb0[0], bb0[1]);
                    mma16(&hacc[20], a1, bb0[2], bb0[3]);
                    mma16(&hacc[24], a1, bb1[0], bb1[1]);
                    mma16(&hacc[28], a1, bb1[2], bb1[3]);
                }
            }

            // ---- hs = fp16(q * relu(hacc + b1)) ----
#pragma unroll
            for (int tm = 0; tm < 2; tm++) {
                int r0 = rbase + tm * 16 + gr;
                float qa = g_q[(size_t)(n0 + r0) * K_ + k];
                float qb = g_q[(size_t)(n0 + r0 + 8) * K_ + k];
#pragma unroll
                for (int tn = 0; tn < 4; tn++) {
                    int idx = (tm * 16 + tn * 4);
                    int c0  = cbase + tn * 8 + 2 * tig;
                    float va0 = fmaxf(hacc[idx + 0] + b1s[c0], 0.f) * qa;
                    float va1 = fmaxf(hacc[idx + 1] + b1s[c0 + 1], 0.f) * qa;
                    float vb0 = fmaxf(hacc[idx + 2] + b1s[c0], 0.f) * qb;
                    float vb1 = fmaxf(hacc[idx + 3] + b1s[c0 + 1], 0.f) * qb;
                    *(__half2*)&hs[r0 * LDHH + c0]       = __floats2half2_rn(va0, va1);
                    *(__half2*)&hs[(r0 + 8) * LDHH + c0] = __floats2half2_rn(vb0, vb1);
                }
            }
            __syncthreads();

            // ========== GEMM2: 2 K-subtiles of 64 ==========================
            ISSUE2(0, 0); CP_COMMIT();
            ISSUE2(1, 1); CP_COMMIT();
            CP_WAIT0();
            __syncthreads();
#pragma unroll
            for (int s = 0; s < 2; s++) {
#pragma unroll
                for (int kk = 0; kk < 4; kk++) {
                    uint32_t a0[4], a1[4], bb0[4], bb1[4];
                    const uint32_t hbse = uHS + (uint32_t)(s * 128 + kk * 32);
                    ldsm4(a0, hbse + (uint32_t)(rbase * (LDHH * 2)) + aOffH);
                    ldsm4(a1, hbse + (uint32_t)((rbase + 16) * (LDHH * 2)) + aOffH);
                    const uint32_t bbse = uST[s] + (uint32_t)(kk * 32);
                    ldsm4(bb0, bbse + (uint32_t)(cbase * PITB) + bOffT);
                    ldsm4(bb1, bbse + (uint32_t)((cbase + 16) * PITB) + bOffT);
                    mma16(&outacc[0],  a0, bb0[0], bb0[1]);
                    mma16(&outacc[4],  a0, bb0[2], bb0[3]);
                    mma16(&outacc[8],  a0, bb1[0], bb1[1]);
                    mma16(&outacc[12], a0, bb1[2], bb1[3]);
                    mma16(&outacc[16], a1, bb0[0], bb0[1]);
                    mma16(&outacc[20], a1, bb0[2], bb0[3]);
                    mma16(&outacc[24], a1, bb1[0], bb1[1]);
                    mma16(&outacc[28], a1, bb1[2], bb1[3]);
                }
            }
        } // ht
    } // experts

    // ---- epilogue: out = outacc + q @ b2 ----
#pragma unroll
    for (int tm = 0; tm < 2; tm++) {
        int r0 = rbase + tm * 16 + gr;
        float qa[K_], qb[K_];
#pragma unroll
        for (int k = 0; k < K_; k++) {
            qa[k] = g_q[(size_t)(n0 + r0) * K_ + k];
            qb[k] = g_q[(size_t)(n0 + r0 + 8) * K_ + k];
        }
#pragma unroll
        for (int tn = 0; tn < 4; tn++) {
            int idx = tm * 16 + tn * 4;
            int c0  = cbase + tn * 8 + 2 * tig;
            float v00 = outacc[idx + 0], v01 = outacc[idx + 1];
            float v10 = outacc[idx + 2], v11 = outacc[idx + 3];
#pragma unroll
            for (int k = 0; k < K_; k++) {
                v00 = fmaf(qa[k], b2s[k * C_ + c0],     v00);
                v01 = fmaf(qa[k], b2s[k * C_ + c0 + 1], v01);
                v10 = fmaf(qb[k], b2s[k * C_ + c0],     v10);
                v11 = fmaf(qb[k], b2s[k * C_ + c0 + 1], v11);
            }
            *(float2*)&out[(size_t)(n0 + r0) * C_ + c0]     = make_float2(v00, v01);
            *(float2*)&out[(size_t)(n0 + r0 + 8) * C_ + c0] = make_float2(v10, v11);
        }
    }
}

// ---------------------------------------------------------------------------
extern "C" void kernel_launch(void* const* d_in, const int* in_sizes, int n_in,
                              void* d_out, int out_size) {
    const float* z  = (const float*)d_in[0];  // [N, NZ]
    const float* mu = (const float*)d_in[1];  // [K, NZ]
    const float* W1 = (const float*)d_in[2];  // [K, NZ, H]
    const float* b1 = (const float*)d_in[3];  // [K, H]
    const float* W2 = (const float*)d_in[4];  // [K, H, C]
    const float* b2 = (const float*)d_in[5];  // [K, C]
    float* out = (float*)d_out;               // [N, C]

    cudaFuncSetAttribute(fused_mma, cudaFuncAttributeMaxDynamicSharedMemorySize, SMEM_DYN);

    prep_kernel<<<NB_Z + NB_T1 + NB_T2 + NB_Q, PREP_TPB>>>(z, mu, W1, W2);
    fused_mma<<<N_ / BM, TPB, SMEM_DYN>>>(b1, b2, out);
}

// round 15
// speedup vs baseline: 2.5746x; 1.0000x over previous
#include <cuda_runtime.h>
#include <cuda_fp16.h>
#include <cstdint>

#define N_  32768
#define NZ_ 512
#define H_  1024
#define C_  128
#define K_  8
#define TPB 512
#define BM  128          // rows per CTA
#define BH  128          // h columns per chunk
#define KS  64           // K depth per stage (fp16: 128B rows)
#define PITB 144         // staging row pitch bytes (128B data + 16 pad)
#define LDHH 136         // hs pitch in halves (272B = 256 data + 16 pad)

// ---------------- device scratch (static globals: allowed) -----------------
__device__ float  g_q[N_ * K_];
__device__ __half g_zth[N_ * NZ_];         // fp16 z
__device__ __half g_w1th[K_ * H_ * NZ_];   // [K][H][NZ]  n-major fp16
__device__ __half g_w2th[K_ * C_ * H_];    // [K][C][H]   n-major fp16

// ---------------- helpers ---------------------------------------------------
__device__ __forceinline__ uint32_t smem_u32(const void* p) {
    uint32_t a;
    asm("{ .reg .u64 t; cvta.to.shared.u64 t, %1; cvt.u32.u64 %0, t; }" : "=r"(a) : "l"(p));
    return a;
}
__device__ __forceinline__ void cp16(uint32_t s, const void* g) {
    asm volatile("cp.async.cg.shared.global [%0], [%1], 16;" :: "r"(s), "l"(g) : "memory");
}
#define CP_COMMIT() asm volatile("cp.async.commit_group;" ::: "memory")
#define CP_WAIT2()  asm volatile("cp.async.wait_group 2;" ::: "memory")
#define CP_WAIT0()  asm volatile("cp.async.wait_group 0;" ::: "memory")

__device__ __forceinline__ void ldsm4(uint32_t* r, uint32_t a) {
    asm volatile("ldmatrix.sync.aligned.m8n8.x4.shared.b16 {%0,%1,%2,%3}, [%4];"
                 : "=r"(r[0]), "=r"(r[1]), "=r"(r[2]), "=r"(r[3]) : "r"(a));
}

// m16n8k16 fp16 mma, fp32 accum. A row-major (4 regs), B col-major [n][k] (2 regs)
__device__ __forceinline__ void mma16(float* c, const uint32_t* a, uint32_t b0, uint32_t b1) {
    asm volatile(
        "mma.sync.aligned.m16n8k16.row.col.f32.f16.f16.f32 "
        "{%0,%1,%2,%3}, {%4,%5,%6,%7}, {%8,%9}, {%0,%1,%2,%3};"
        : "+f"(c[0]), "+f"(c[1]), "+f"(c[2]), "+f"(c[3])
        : "r"(a[0]), "r"(a[1]), "r"(a[2]), "r"(a[3]), "r"(b0), "r"(b1));
}

// ---------------------------------------------------------------------------
// prep_kernel: z->fp16, W1/W2 transpose->fp16 n-major, q.  One kernel.
// ---------------------------------------------------------------------------
#define PREP_TPB 256
#define NB_Z  16384
#define NB_T1 4096
#define NB_T2 1024
#define NB_Q  4096

__global__ void prep_kernel(const float* __restrict__ z, const float* __restrict__ mu,
                            const float* __restrict__ W1, const float* __restrict__ W2) {
    __shared__ float t[32][33];
    __shared__ float smu[K_ * NZ_];
    const int bid = blockIdx.x;
    const int tid = threadIdx.x;

    if (bid < NB_Z) {
        int i = bid * PREP_TPB + tid;      // float4 index
        float4 v = ((const float4*)z)[i];
        __half2* dst = (__half2*)g_zth;
        dst[2 * i]     = __floats2half2_rn(v.x, v.y);
        dst[2 * i + 1] = __floats2half2_rn(v.z, v.w);
        return;
    }
    if (bid < NB_Z + NB_T1) {              // W1 [K,NZ,H] -> g_w1th [K,H,NZ]
        int i = bid - NB_Z;
        int xx = i & 31, yy = (i >> 5) & 15, b = i >> 9;
        int r0 = yy * 32, c0 = xx * 32;
        const float* s = W1 + (size_t)b * NZ_ * H_;
        __half* d = g_w1th + (size_t)b * NZ_ * H_;
        int tx = tid & 31, ty = tid >> 5;
#pragma unroll
        for (int ii = 0; ii < 32; ii += 8)
            t[ty + ii][tx] = s[(size_t)(r0 + ty + ii) * H_ + c0 + tx];
        __syncthreads();
#pragma unroll
        for (int ii = 0; ii < 32; ii += 8)
            d[(size_t)(c0 + ty + ii) * NZ_ + r0 + tx] = __float2half_rn(t[tx][ty + ii]);
        return;
    }
    if (bid < NB_Z + NB_T1 + NB_T2) {      // W2 [K,H,C] -> g_w2th [K,C,H]
        int i = bid - NB_Z - NB_T1;
        int xx = i & 3, yy = (i >> 2) & 31, b = i >> 7;
        int r0 = yy * 32, c0 = xx * 32;
        const float* s = W2 + (size_t)b * H_ * C_;
        __half* d = g_w2th + (size_t)b * H_ * C_;
        int tx = tid & 31, ty = tid >> 5;
#pragma unroll
        for (int ii = 0; ii < 32; ii += 8)
            t[ty + ii][tx] = s[(size_t)(r0 + ty + ii) * C_ + c0 + tx];
        __syncthreads();
#pragma unroll
        for (int ii = 0; ii < 32; ii += 8)
            d[(size_t)(c0 + ty + ii) * H_ + r0 + tx] = __float2half_rn(t[tx][ty + ii]);
        return;
    }
    {   // q
        int qb = bid - NB_Z - NB_T1 - NB_T2;
        for (int i = tid; i < K_ * NZ_; i += PREP_TPB) smu[i] = mu[i];
        __syncthreads();
        int gwarp = (qb * PREP_TPB + tid) >> 5;
        int lane  = tid & 31;
        if (gwarp >= N_) return;
        const float* zr = z + (size_t)gwarp * NZ_;
        float acc[K_];
#pragma unroll
        for (int k = 0; k < K_; k++) acc[k] = 0.f;
        for (int j = lane; j < NZ_; j += 32) {
            float zj = zr[j];
#pragma unroll
            for (int k = 0; k < K_; k++) {
                float d = zj - smu[k * NZ_ + j];
                acc[k] = fmaf(d, d, acc[k]);
            }
        }
#pragma unroll
        for (int k = 0; k < K_; k++)
#pragma unroll
            for (int o = 16; o > 0; o >>= 1)
                acc[k] += __shfl_xor_sync(0xffffffffu, acc[k], o);
        if (lane == 0) {
            float w[K_], s = 0.f;
#pragma unroll
            for (int k = 0; k < K_; k++) { w[k] = 1.f / (1.f + acc[k]); s += w[k]; }
            float inv = 1.f / s;
#pragma unroll
            for (int k = 0; k < K_; k++) g_q[gwarp * K_ + k] = w[k] * inv;
        }
    }
}

// ---------------------------------------------------------------------------
// fused fp16 mma: 512 threads, 4x4 warps, 32x32 tiles, m16n8k16,
// 4-stage cp.async + in-register fragment double-buffering.
// ---------------------------------------------------------------------------
#define STG_BYTES (2 * 128 * PITB)            // A 18432 + B 18432 = 36864
#define OFF_HS    (4 * STG_BYTES)             // 147456
#define OFF_B2S   (OFF_HS + 128 * LDHH * 2)   // 182272
#define OFF_B1S   (OFF_B2S + 4096)            // 186368
#define SMEM_DYN  (OFF_B1S + 512)             // 186880

#define ISSUE1(ss, st) do {                                                   \
    const int zb_ = (ss) * KS;                                                \
    const uint32_t ua_ = uST[st];                                             \
    const uint32_t ub_ = uST[st] + 128 * PITB;                                \
    _Pragma("unroll")                                                         \
    for (int v = 0; v < 2; v++) {                                             \
        int lin = tid + v * TPB;                                              \
        int row = lin >> 3, seg = lin & 7;                                    \
        cp16(ua_ + row * PITB + seg * 16,                                     \
             g_zth + (size_t)(n0 + row) * NZ_ + zb_ + seg * 8);               \
    }                                                                         \
    _Pragma("unroll")                                                         \
    for (int v = 0; v < 2; v++) {                                             \
        int lin = tid + v * TPB;                                              \
        int row = lin >> 3, seg = lin & 7;                                    \
        cp16(ub_ + row * PITB + seg * 16,                                     \
             w1base + (size_t)(ht + row) * NZ_ + zb_ + seg * 8);              \
    }                                                                         \
} while (0)

#define ISSUE2(ss, st) do {                                                   \
    const int hb_ = (ss) * KS;                                                \
    const uint32_t ub_ = uST[st];                                             \
    _Pragma("unroll")                                                         \
    for (int v = 0; v < 2; v++) {                                             \
        int lin = tid + v * TPB;                                              \
        int row = lin >> 3, seg = lin & 7;                                    \
        cp16(ub_ + row * PITB + seg * 16,                                     \
             w2base + (size_t)row * H_ + ht + hb_ + seg * 8);                 \
    }                                                                         \
} while (0)

// load all fragments of k16-block kk from GEMM1 stage st into reg buffer bf
#define LDFRAG1(bf, st, kk) do {                                              \
    const uint32_t ab_ = uST[st] + (uint32_t)((kk) * 32);                     \
    ldsm4(&fa[bf][0], ab_ + (uint32_t)(rbase * PITB) + aOffT);                \
    ldsm4(&fa[bf][4], ab_ + (uint32_t)((rbase + 16) * PITB) + aOffT);         \
    const uint32_t bs_ = uST[st] + (uint32_t)(128 * PITB) + (uint32_t)((kk) * 32); \
    ldsm4(&fb[bf][0], bs_ + (uint32_t)(cbase * PITB) + bOffT);                \
    ldsm4(&fb[bf][4], bs_ + (uint32_t)((cbase + 16) * PITB) + bOffT);         \
} while (0)

// load fragments of k16-block kk of GEMM2 subtile s (A from hs, B from stage s)
#define LDFRAG2(bf, s_, kk) do {                                              \
    const uint32_t hb_ = uHS + (uint32_t)(((s_) * 128 + (kk) * 32));          \
    ldsm4(&fa[bf][0], hb_ + (uint32_t)(rbase * (LDHH * 2)) + aOffH);          \
    ldsm4(&fa[bf][4], hb_ + (uint32_t)((rbase + 16) * (LDHH * 2)) + aOffH);   \
    const uint32_t bs_ = uST[s_] + (uint32_t)((kk) * 32);                     \
    ldsm4(&fb[bf][0], bs_ + (uint32_t)(cbase * PITB) + bOffT);                \
    ldsm4(&fb[bf][4], bs_ + (uint32_t)((cbase + 16) * PITB) + bOffT);         \
} while (0)

#define MMABLK(acc, bf) do {                                                  \
    mma16(&(acc)[0],  &fa[bf][0], fb[bf][0], fb[bf][1]);                      \
    mma16(&(acc)[4],  &fa[bf][0], fb[bf][2], fb[bf][3]);                      \
    mma16(&(acc)[8],  &fa[bf][0], fb[bf][4], fb[bf][5]);                      \
    mma16(&(acc)[12], &fa[bf][0], fb[bf][6], fb[bf][7]);                      \
    mma16(&(acc)[16], &fa[bf][4], fb[bf][0], fb[bf][1]);                      \
    mma16(&(acc)[20], &fa[bf][4], fb[bf][2], fb[bf][3]);                      \
    mma16(&(acc)[24], &fa[bf][4], fb[bf][4], fb[bf][5]);                      \
    mma16(&(acc)[28], &fa[bf][4], fb[bf][6], fb[bf][7]);                      \
} while (0)

__global__ void __launch_bounds__(TPB, 1) fused_mma(
    const float* __restrict__ b1, const float* __restrict__ b2,
    float* __restrict__ out)
{
    extern __shared__ char sm[];
    __half* const hs  = (__half*)(sm + OFF_HS);
    float*  const b2s = (float*)(sm + OFF_B2S);
    float*  const b1s = (float*)(sm + OFF_B1S);

    const uint32_t sb = smem_u32(sm);
    const uint32_t uST[4] = { sb, sb + STG_BYTES, sb + 2 * STG_BYTES, sb + 3 * STG_BYTES };
    const uint32_t uHS = sb + OFF_HS;

    const int tid  = threadIdx.x;
    const int lane = tid & 31;
    const int warp = tid >> 5;       // 0..15
    const int wm   = warp & 3;       // row block of 32
    const int wn   = warp >> 2;      // col block of 32
    const int gr   = lane >> 2;      // 0..7
    const int tig  = lane & 3;       // 0..3
    const int rbase = wm * 32;
    const int cbase = wn * 32;
    const int n0   = blockIdx.x * BM;

    // ldmatrix lane offsets (bytes)
    const int lr = lane & 7;
    const int lg = lane >> 3;
    const uint32_t aOffT = (uint32_t)((lr + (lg & 1) * 8) * PITB + (lg >> 1) * 16);
    const uint32_t aOffH = (uint32_t)((lr + (lg & 1) * 8) * (LDHH * 2) + (lg >> 1) * 16);
    const uint32_t bOffT = (uint32_t)((lr + (lg >> 1) * 8) * PITB + (lg & 1) * 16);

    for (int i = tid; i < K_ * C_; i += TPB) b2s[i] = b2[i];

    float outacc[32];
#pragma unroll
    for (int i = 0; i < 32; i++) outacc[i] = 0.f;

    uint32_t fa[2][8], fb[2][8];     // double-buffered fragments

    for (int k = 0; k < K_; k++) {
        const __half* w1base = g_w1th + (size_t)k * H_ * NZ_;
        const __half* w2base = g_w2th + (size_t)k * C_ * H_;

        for (int ht = 0; ht < H_; ht += BH) {
            __syncthreads();   // prev chunk fully consumed
            if (tid < BH) b1s[tid] = b1[k * H_ + ht + tid];

            float hacc[32];
#pragma unroll
            for (int i = 0; i < 32; i++) hacc[i] = 0.f;

            // ========== GEMM1: 8 K-subtiles of 64, 4-stage pipeline ========
            ISSUE1(0, 0); CP_COMMIT();
            ISSUE1(1, 1); CP_COMMIT();
            ISSUE1(2, 2); CP_COMMIT();
            for (int s = 0; s < 8; s++) {
                const int st = s & 3;
                CP_WAIT2();
                __syncthreads();
                if (s < 5) { ISSUE1(s + 3, (s + 3) & 3); }
                CP_COMMIT();
                // fragment-pipelined compute over 4 k16 blocks
                LDFRAG1(0, st, 0);
                LDFRAG1(1, st, 1);
                MMABLK(hacc, 0);
                LDFRAG1(0, st, 2);
                MMABLK(hacc, 1);
                LDFRAG1(1, st, 3);
                MMABLK(hacc, 0);
                MMABLK(hacc, 1);
            }

            // ---- hs = fp16(q * relu(hacc + b1)) ----
#pragma unroll
            for (int tm = 0; tm < 2; tm++) {
                int r0 = rbase + tm * 16 + gr;
                float qa = g_q[(size_t)(n0 + r0) * K_ + k];
                float qb = g_q[(size_t)(n0 + r0 + 8) * K_ + k];
#pragma unroll
                for (int tn = 0; tn < 4; tn++) {
                    int idx = (tm * 16 + tn * 4);
                    int c0  = cbase + tn * 8 + 2 * tig;
                    float va0 = fmaxf(hacc[idx + 0] + b1s[c0], 0.f) * qa;
                    float va1 = fmaxf(hacc[idx + 1] + b1s[c0 + 1], 0.f) * qa;
                    float vb0 = fmaxf(hacc[idx + 2] + b1s[c0], 0.f) * qb;
                    float vb1 = fmaxf(hacc[idx + 3] + b1s[c0 + 1], 0.f) * qb;
                    *(__half2*)&hs[r0 * LDHH + c0]       = __floats2half2_rn(va0, va1);
                    *(__half2*)&hs[(r0 + 8) * LDHH + c0] = __floats2half2_rn(vb0, vb1);
                }
            }
            __syncthreads();

            // ========== GEMM2: 2 K-subtiles of 64 ==========================
            ISSUE2(0, 0); CP_COMMIT();
            ISSUE2(1, 1); CP_COMMIT();
            CP_WAIT0();
            __syncthreads();
#pragma unroll
            for (int s = 0; s < 2; s++) {
                LDFRAG2(0, s, 0);
                LDFRAG2(1, s, 1);
                MMABLK(outacc, 0);
                LDFRAG2(0, s, 2);
                MMABLK(outacc, 1);
                LDFRAG2(1, s, 3);
                MMABLK(outacc, 0);
                MMABLK(outacc, 1);
            }
        } // ht
    } // experts

    // ---- epilogue: out = outacc + q @ b2 ----
#pragma unroll
    for (int tm = 0; tm < 2; tm++) {
        int r0 = rbase + tm * 16 + gr;
        float qa[K_], qb[K_];
#pragma unroll
        for (int k = 0; k < K_; k++) {
            qa[k] = g_q[(size_t)(n0 + r0) * K_ + k];
            qb[k] = g_q[(size_t)(n0 + r0 + 8) * K_ + k];
        }
#pragma unroll
        for (int tn = 0; tn < 4; tn++) {
            int idx = tm * 16 + tn * 4;
            int c0  = cbase + tn * 8 + 2 * tig;
            float v00 = outacc[idx + 0], v01 = outacc[idx + 1];
            float v10 = outacc[idx + 2], v11 = outacc[idx + 3];
#pragma unroll
            for (int k = 0; k < K_; k++) {
                v00 = fmaf(qa[k], b2s[k * C_ + c0],     v00);
                v01 = fmaf(qa[k], b2s[k * C_ + c0 + 1], v01);
                v10 = fmaf(qb[k], b2s[k * C_ + c0],     v10);
                v11 = fmaf(qb[k], b2s[k * C_ + c0 + 1], v11);
            }
            *(float2*)&out[(size_t)(n0 + r0) * C_ + c0]     = make_float2(v00, v01);
            *(float2*)&out[(size_t)(n0 + r0 + 8) * C_ + c0] = make_float2(v10, v11);
        }
    }
}

// ---------------------------------------------------------------------------
extern "C" void kernel_launch(void* const* d_in, const int* in_sizes, int n_in,
                              void* d_out, int out_size) {
    const float* z  = (const float*)d_in[0];  // [N, NZ]
    const float* mu = (const float*)d_in[1];  // [K, NZ]
    const float* W1 = (const float*)d_in[2];  // [K, NZ, H]
    const float* b1 = (const float*)d_in[3];  // [K, H]
    const float* W2 = (const float*)d_in[4];  // [K, H, C]
    const float* b2 = (const float*)d_in[5];  // [K, C]
    float* out = (float*)d_out;               // [N, C]

    cudaFuncSetAttribute(fused_mma, cudaFuncAttributeMaxDynamicSharedMemorySize, SMEM_DYN);

    prep_kernel<<<NB_Z + NB_T1 + NB_T2 + NB_Q, PREP_TPB>>>(z, mu, W1, W2);
    fused_mma<<<N_ / BM, TPB, SMEM_DYN>>>(b1, b2, out);
}